// round 9
// baseline (speedup 1.0000x reference)
#include <cuda_runtime.h>

// ISTA deconvolution (round 9): parity-split conv + ping-pong buffers +
// balanced persistent grid.
//  - conv_split (verified R6/R7 math): single pair-planar E array per signal;
//    17 FFMA2 per k-pair, 1 LDS.64 refill + 1 LDS.128 (h) per k-pair.
//  - Two 17KB buffers (sh_y for y, sh_r for residual) -> residual written to
//    the OTHER buffer => only 2 __syncthreads per row (after stage, before conv2).
//  - 444 persistent CTAs (148 SM x 3); bid<100 take 10 rows, others 9
//    (start = 9*bid + min(bid,100)) -> per-SM load 27-28 rows, ~3% tail.
//  - Closed-form ISTA epilogue: x_T = T*sign(su)*max(|su|-lambda, 0).

#define BDIM 4096
#define LDIM 4096
#define KW   128
#define NTH  256
#define NCTA 444
#define PPL8 266                 // ull per plane
#define NPAIR_ULL (8 * PPL8)     // 2128
#define LAMBDA 0.1f
#define TITER  5.0f

typedef unsigned long long ull;

__device__ __forceinline__ ull pk2(float lo, float hi) {
    ull r;
    asm("mov.b64 %0, {%1, %2};" : "=l"(r) : "f"(lo), "f"(hi));
    return r;
}
__device__ __forceinline__ void unpk2(ull v, float& lo, float& hi) {
    asm("mov.b64 {%0, %1}, %2;" : "=f"(lo), "=f"(hi) : "l"(v));
}
__device__ __forceinline__ ull fma2(ull a, ull b, ull c) {
    ull d;
    asm("fma.rn.f32x2 %0, %1, %2, %3;" : "=l"(d) : "l"(a), "l"(b), "l"(c));
    return d;
}

// ull index of pair p = 8t + c inside a pair-planar array.
#define PIDX(c, t) ((((c) & 7) * PPL8) + ((c) >> 3) + (t))

// Tap-parity-split convolution (full unroll):
//   eacc[q] = sum_m h[2m]  *E[8t+q+m] -> (c_e[16t+2q],   c_e[16t+2q+1])
//   oa[j]   = sum_m h[2m+1]*E[8t+j+m] -> (c_o[16t+2j-1], c_o[16t+2j])
// Unguarded reads up to pair 8t+71 (max 2111) covered by zero pads; hq[64]
// is a zero pad for the unguarded h prefetch.
__device__ __forceinline__ void conv_split(const ull* __restrict__ ep,
                                           const ulonglong2* __restrict__ hq,
                                           int t,
                                           ull* __restrict__ eacc,
                                           ull* __restrict__ oa)
{
    ull E[8];
#pragma unroll
    for (int c = 0; c < 8; c++) E[c] = ep[c * PPL8 + t];
#pragma unroll
    for (int q = 0; q < 8; q++) eacc[q] = 0ull;
#pragma unroll
    for (int j = 0; j < 9; j++) oa[j] = 0ull;

    ulonglong2 hh = hq[0];
#pragma unroll
    for (int m = 0; m < KW / 2; m++) {
        ull Enew = ep[PIDX(m + 8, t)];
        ulonglong2 hn = hq[m + 1];
#pragma unroll
        for (int q = 0; q < 8; q++) {
            ull Eq = E[(m + q) & 7];
            eacc[q] = fma2(Eq, hh.x, eacc[q]);
            oa[q]   = fma2(Eq, hh.y, oa[q]);
        }
        oa[8] = fma2(Enew, hh.y, oa[8]);
        E[m & 7] = Enew;
        hh = hn;
    }
}

__global__ __launch_bounds__(NTH, 3)
void ista_persistent_kernel(const float* __restrict__ y,
                            const float* __restrict__ h,
                            const float* __restrict__ step,
                            float* __restrict__ out)
{
    __shared__ __align__(16) ull sh_y[NPAIR_ULL];   // y row, E pairs
    __shared__ __align__(16) ull sh_r[NPAIR_ULL];   // residual, E pairs
    __shared__ __align__(16) ulonglong2 sh_h[KW / 2 + 1];
    __shared__ __align__(16) ulonglong2 sh_hr[KW / 2 + 1];

    const int t = threadIdx.x;
    const int bid = blockIdx.x;
    const float s = __ldg(step);
    float* yf = reinterpret_cast<float*>(sh_y);
    float* rf = reinterpret_cast<float*>(sh_r);

    // ---- once per CTA: zero both arrays (covers all pads), stage h ----
    for (int i = t; i < NPAIR_ULL; i += NTH) { sh_y[i] = 0ull; sh_r[i] = 0ull; }
    if (t < KW / 2) {
        float a0 = h[2 * t], a1 = h[2 * t + 1];
        sh_h[t] = make_ulonglong2(pk2(a0, a0), pk2(a1, a1));
        float b0 = h[KW - 1 - 2 * t], b1 = h[KW - 2 - 2 * t];   // reversed
        sh_hr[t] = make_ulonglong2(pk2(b0, b0), pk2(b1, b1));
    }
    if (t == KW / 2) {
        sh_h[KW / 2]  = make_ulonglong2(0ull, 0ull);
        sh_hr[KW / 2] = make_ulonglong2(0ull, 0ull);
    }

    // Balanced row assignment: bid<100 -> 10 rows, else 9 (444*9+100 = 4096).
    const int heavy = (bid < 100) ? 1 : 0;
    const int row0 = 9 * bid + (heavy ? bid : 100);
    const int nrows = 9 + heavy;

    for (int r = 0; r < nrows; r++) {
        const int row = row0 + r;
        const float* yr = y + (long long)row * LDIM;

        // Stage y (16 floats/thread) into sh_y: xp[j] = y[j-63];
        // thread t owns y[16t..16t+15] -> pairs 8t+31(hi) .. 8t+39(lo).
        // Safe to write: every thread passed the pre-conv2 sync of the
        // previous row before reaching here, so all conv1 reads of sh_y
        // are complete. Pads (zeroed at init) are never touched.
        {
            float v[16];
            const float4* y4 = reinterpret_cast<const float4*>(yr + 16 * t);
#pragma unroll
            for (int i = 0; i < 4; i++) {
                float4 f = __ldg(y4 + i);
                v[4 * i + 0] = f.x; v[4 * i + 1] = f.y;
                v[4 * i + 2] = f.z; v[4 * i + 3] = f.w;
            }
#pragma unroll
            for (int i = 0; i < 7; i++)
                sh_y[PIDX(32 + i, t)] = pk2(v[2 * i + 1], v[2 * i + 2]);
            yf[2 * PIDX(31, t) + 1] = v[0];
            yf[2 * PIDX(39, t) + 0] = v[15];
        }
        __syncthreads();   // sh_y fully staged (also: first iter -> init done)

        // ---- Stage 1: conv(y, h) ----
        ull eacc[8], oa[9];
        conv_split(sh_y, sh_h, t, eacc, oa);

        // Recover y scalars from own staged pairs (no cross-thread hazard):
        // y[16t+2q] = hi(pair 8t+31+q); y[16t+2q+1] = lo(pair 8t+32+q).
        ull P[9];
#pragma unroll
        for (int q = 0; q < 9; q++) P[q] = sh_y[PIDX(31 + q, t)];

        float ro[16];
#pragma unroll
        for (int q = 0; q < 8; q++) {
            float el, eh, ol0, oh0, ol1, oh1, plo, phi, nlo, nhi;
            unpk2(eacc[q], el, eh);
            unpk2(oa[q],     ol0, oh0);   // (c_o[16t+2q-1], c_o[16t+2q])
            unpk2(oa[q + 1], ol1, oh1);   // (c_o[16t+2q+1], c_o[16t+2q+2])
            unpk2(P[q],     plo, phi);    // phi = y[16t+2q]
            unpk2(P[q + 1], nlo, nhi);    // nlo = y[16t+2q+1]
            ro[2 * q + 0] = phi - (el + oh0);
            ro[2 * q + 1] = nlo - (eh + ol1);
        }

        // Write residual into sh_r (different buffer -> no sync needed first).
#pragma unroll
        for (int i = 0; i < 7; i++)
            sh_r[PIDX(32 + i, t)] = pk2(ro[2 * i + 1], ro[2 * i + 2]);
        rf[2 * PIDX(31, t) + 1] = ro[0];
        rf[2 * PIDX(39, t) + 0] = ro[15];
        __syncthreads();   // sh_r fully written; all conv1 reads of sh_y done

        // ---- Stage 2: conv(resid, h_rev) + closed-form ISTA epilogue ----
        conv_split(sh_r, sh_hr, t, eacc, oa);

        float xo[16];
#pragma unroll
        for (int q = 0; q < 8; q++) {
            float el, eh, ol0, oh0, ol1, oh1;
            unpk2(eacc[q], el, eh);
            unpk2(oa[q],     ol0, oh0);
            unpk2(oa[q + 1], ol1, oh1);
            float a0 = s * (el + oh0);
            float a1 = s * (eh + ol1);
            xo[2 * q + 0] = copysignf(TITER * fmaxf(fabsf(a0) - LAMBDA, 0.0f), a0);
            xo[2 * q + 1] = copysignf(TITER * fmaxf(fabsf(a1) - LAMBDA, 0.0f), a1);
        }
        float4* o4 = reinterpret_cast<float4*>(out + (long long)row * LDIM + 16 * t);
#pragma unroll
        for (int i = 0; i < 4; i++)
            o4[i] = make_float4(xo[4 * i], xo[4 * i + 1], xo[4 * i + 2], xo[4 * i + 3]);
        // No sync here: next iteration's sh_y staging is safe because every
        // thread finished its conv1 reads before the pre-conv2 sync above,
        // and conv2/epilogue touch only sh_r / global memory.
    }
}

extern "C" void kernel_launch(void* const* d_in, const int* in_sizes, int n_in,
                              void* d_out, int out_size)
{
    const float* y = nullptr;
    const float* h = nullptr;
    const float* s = nullptr;
    for (int i = 0; i < n_in; i++) {
        if (in_sizes[i] == BDIM * LDIM)      y = (const float*)d_in[i];
        else if (in_sizes[i] == KW)          h = (const float*)d_in[i];
        else if (in_sizes[i] == 1)           s = (const float*)d_in[i];
    }
    ista_persistent_kernel<<<NCTA, NTH>>>(y, h, s, (float*)d_out);
}

// round 10
// speedup vs baseline: 1.0964x; 1.0964x over previous
#include <cuda_runtime.h>

// ISTA deconvolution (round 10): R2 skeleton (best, 162us) + latency fixes.
//  - 9-slot E/O register rings, refill loaded 2 iterations before first use,
//    written into the slot freed by the q=0 FMA (WAR-safe, zero MOVs; all
//    ring indices (m+q)%9 are compile-time under full unroll).
//  - h as interleaved dup-pair ulonglong2, one LDS.128 per k-pair, prefetched
//    one iteration ahead (entry 64 is a zero pad for the unguarded prefetch).
//  - Single prologue barrier: pad zeroing is word-exact and disjoint from all
//    staging writes. 3 syncs/row total.
//  - grid = 4096 CTAs (persistence falsified in R8/R9).
//  - Closed-form ISTA epilogue: x_T = T*sign(su)*max(|su|-lambda, 0).

#define BDIM 4096
#define LDIM 4096
#define KW   128
#define NTH  256
#define PPL8 266                 // ull per plane
#define NPAIR_ULL (8 * PPL8)     // 2128 ull per pair array
#define LAMBDA 0.1f
#define TITER  5.0f

typedef unsigned long long ull;

__device__ __forceinline__ ull pk2(float lo, float hi) {
    ull r;
    asm("mov.b64 %0, {%1, %2};" : "=l"(r) : "f"(lo), "f"(hi));
    return r;
}
__device__ __forceinline__ void unpk2(ull v, float& lo, float& hi) {
    asm("mov.b64 {%0, %1}, %2;" : "=f"(lo), "=f"(hi) : "l"(v));
}
__device__ __forceinline__ ull fma2(ull a, ull b, ull c) {
    ull d;
    asm("fma.rn.f32x2 %0, %1, %2, %3;" : "=l"(d) : "l"(a), "l"(b), "l"(c));
    return d;
}

// ull index of pair p = 8t + c inside a pair-planar array.
#define PIDX(c, t) ((((c) & 7) * PPL8) + ((c) >> 3) + (t))

// 16 outputs (8 f32x2 accumulators) per thread. 9-slot rings; refill for
// iteration m+2 is issued at iteration m, right after the q=0 FMAs free the
// slot. Reads reach pair 8t+72 (zero-padded); hq[64] is a zero pad.
__device__ __forceinline__ void conv16(const ull* __restrict__ ep,
                                       const ull* __restrict__ op,
                                       const ulonglong2* __restrict__ hq,
                                       int t, ull* __restrict__ acc)
{
    ull E[9], O[9];
#pragma unroll
    for (int c = 0; c < 9; c++) {
        E[c] = ep[PIDX(c, t)];
        O[c] = op[PIDX(c, t)];
    }
#pragma unroll
    for (int q = 0; q < 8; q++) acc[q] = 0ull;

    ulonglong2 hh = hq[0];
#pragma unroll
    for (int m = 0; m < KW / 2; m++) {
        ulonglong2 hn = hq[m + 1];
        // q = 0 first: frees ring slot m%9 (holds pair 8t+m, last use here).
        acc[0] = fma2(E[m % 9], hh.x, acc[0]);
        acc[0] = fma2(O[m % 9], hh.y, acc[0]);
        // Refill freed slot with pair 8t+m+9 (first consumed at iter m+2,
        // q=7). Issued after the q=0 reads -> WAR-safe, ~2 iterations of
        // latency budget for the LDS.
        E[m % 9] = ep[PIDX(m + 9, t)];
        O[m % 9] = op[PIDX(m + 9, t)];
#pragma unroll
        for (int q = 1; q < 8; q++) {
            acc[q] = fma2(E[(m + q) % 9], hh.x, acc[q]);
            acc[q] = fma2(O[(m + q) % 9], hh.y, acc[q]);
        }
        hh = hn;
    }
}

__global__ __launch_bounds__(NTH, 3)
void ista_row_kernel(const float* __restrict__ y,
                     const float* __restrict__ h,
                     const float* __restrict__ step,
                     float* __restrict__ out)
{
    __shared__ __align__(16) ull sh_ep[NPAIR_ULL];
    __shared__ __align__(16) ull sh_op[NPAIR_ULL];
    __shared__ __align__(16) ulonglong2 sh_h[KW / 2 + 1];   // dup pairs fwd (+pad)
    __shared__ __align__(16) ulonglong2 sh_hr[KW / 2 + 1];  // dup pairs rev (+pad)

    const int t = threadIdx.x;
    const int row = blockIdx.x;
    const float* yr = y + (long long)row * LDIM;
    const float s = __ldg(step);
    float* epf = reinterpret_cast<float*>(sh_ep);
    float* opf = reinterpret_cast<float*>(sh_op);

    // ---- prologue: word-exact pad zeroing + h staging + y staging, ONE sync.
    // All writes are to disjoint 32-bit words.
    // Staged coverage: O pairs [31,2079) full; E pairs [32,2079) full,
    // pair 31 hi-only, pair 2079 lo-only. Conv reads pairs [0,2113).
    if (t < 31) {                               // E pairs [0,31) full zero
        sh_ep[(t & 7) * PPL8 + (t >> 3)] = 0ull;
    } else if (t < 62) {                        // O pairs [0,31) full zero
        int p = t - 31;
        sh_op[(p & 7) * PPL8 + (p >> 3)] = 0ull;
    } else if (t == 62) {                       // E pair 31: lo half zero
        epf[2 * (7 * PPL8 + 3) + 0] = 0.0f;
    } else if (t == 63) {                       // E pair 2079: hi half zero
        epf[2 * (7 * PPL8 + 259) + 1] = 0.0f;
    } else if (t < 97) {                        // E pairs [2080,2113) full zero
        int j = t - 64;                         // 2080 % 8 == 0
        sh_ep[(j & 7) * PPL8 + 260 + (j >> 3)] = 0ull;
    } else if (t < 131) {                       // O pairs [2079,2113) full zero
        int p = 2079 + (t - 97);
        sh_op[(p & 7) * PPL8 + (p >> 3)] = 0ull;
    } else if (t >= 160 && t < 160 + KW / 2) {  // h dup pairs
        int u = t - 160;
        float a0 = h[2 * u], a1 = h[2 * u + 1];
        sh_h[u] = make_ulonglong2(pk2(a0, a0), pk2(a1, a1));
        float b0 = h[KW - 1 - 2 * u], b1 = h[KW - 2 - 2 * u];   // reversed
        sh_hr[u] = make_ulonglong2(pk2(b0, b0), pk2(b1, b1));
    } else if (t == 160 + KW / 2) {             // zero pads for h prefetch
        sh_h[KW / 2]  = make_ulonglong2(0ull, 0ull);
        sh_hr[KW / 2] = make_ulonglong2(0ull, 0ull);
    }

    // Stage y (16 floats/thread): xp[j] = y[j-63];
    // thread t owns y[16t..16t+15] -> pairs 8t+31 .. 8t+39.
    {
        float v[16];
        const float4* y4 = reinterpret_cast<const float4*>(yr + 16 * t);
#pragma unroll
        for (int i = 0; i < 4; i++) {
            float4 f = __ldg(y4 + i);
            v[4 * i + 0] = f.x; v[4 * i + 1] = f.y;
            v[4 * i + 2] = f.z; v[4 * i + 3] = f.w;
        }
#pragma unroll
        for (int i = 0; i < 8; i++)   // opairs[8t+31+i] = (v[2i], v[2i+1])
            sh_op[PIDX(31 + i, t)] = pk2(v[2 * i], v[2 * i + 1]);
#pragma unroll
        for (int i = 0; i < 7; i++)   // epairs[8t+32+i] = (v[2i+1], v[2i+2])
            sh_ep[PIDX(32 + i, t)] = pk2(v[2 * i + 1], v[2 * i + 2]);
        epf[2 * PIDX(31, t) + 1] = v[0];    // hi of epair 8t+31
        epf[2 * PIDX(39, t) + 0] = v[15];   // lo of epair 8t+39
    }
    __syncthreads();

    // ---- Stage 1: conv(y, h); residual = y - conv ----
    ull acc[8];
    conv16(sh_ep, sh_op, sh_h, t, acc);

    ull r2[8];
    {
        const ull neg1 = pk2(-1.0f, -1.0f);
#pragma unroll
        for (int q = 0; q < 8; q++) {
            ull yp = sh_op[PIDX(31 + q, t)];   // (y[16t+2q], y[16t+2q+1])
            r2[q] = fma2(acc[q], neg1, yp);    // resid = y - conv
        }
    }
    __syncthreads();   // all conv1 + y-pair reads done before overwrite

    // Overwrite pair arrays with residual (identical geometry; pads stay 0).
    {
        float lo[8], hi[8];
#pragma unroll
        for (int q = 0; q < 8; q++) unpk2(r2[q], lo[q], hi[q]);
#pragma unroll
        for (int q = 0; q < 8; q++)
            sh_op[PIDX(31 + q, t)] = r2[q];
#pragma unroll
        for (int i = 0; i < 7; i++)
            sh_ep[PIDX(32 + i, t)] = pk2(hi[i], lo[i + 1]);
        epf[2 * PIDX(31, t) + 1] = lo[0];
        epf[2 * PIDX(39, t) + 0] = hi[7];
    }
    __syncthreads();

    // ---- Stage 2: conv(resid, h_rev) + closed-form ISTA epilogue ----
    conv16(sh_ep, sh_op, sh_hr, t, acc);

    float xo[16];
#pragma unroll
    for (int q = 0; q < 8; q++) {
        float u0, u1;
        unpk2(acc[q], u0, u1);
        float a0 = s * u0;
        float a1 = s * u1;
        xo[2 * q + 0] = copysignf(TITER * fmaxf(fabsf(a0) - LAMBDA, 0.0f), a0);
        xo[2 * q + 1] = copysignf(TITER * fmaxf(fabsf(a1) - LAMBDA, 0.0f), a1);
    }
    float4* o4 = reinterpret_cast<float4*>(out + (long long)row * LDIM + 16 * t);
#pragma unroll
    for (int i = 0; i < 4; i++)
        o4[i] = make_float4(xo[4 * i], xo[4 * i + 1], xo[4 * i + 2], xo[4 * i + 3]);
}

extern "C" void kernel_launch(void* const* d_in, const int* in_sizes, int n_in,
                              void* d_out, int out_size)
{
    const float* y = nullptr;
    const float* h = nullptr;
    const float* s = nullptr;
    for (int i = 0; i < n_in; i++) {
        if (in_sizes[i] == BDIM * LDIM)      y = (const float*)d_in[i];
        else if (in_sizes[i] == KW)          h = (const float*)d_in[i];
        else if (in_sizes[i] == 1)           s = (const float*)d_in[i];
    }
    ista_row_kernel<<<BDIM, NTH>>>(y, h, s, (float*)d_out);
}